// round 15
// baseline (speedup 1.0000x reference)
#include <cuda_runtime.h>
#include <cuda_fp16.h>
#include <cstdint>

#define BB 8
#define NN 512
#define NROWS (BB * NN)   // 4096

// ---------------- scratch (device globals; no allocation allowed) ----------
__device__ float g_h[NROWS * 128];
__device__ float g_ui[NROWS * 64];
__device__ float g_uj[NROWS * 64];
__device__ float g_upd[NROWS * 259];
__device__ unsigned short g_wh[64 * 64];   // aw1^T fp16, [kk][k]

// ---------------- helpers ---------------------------------------------------
__device__ __forceinline__ uint32_t smem_u32(const void* p) {
    uint32_t a;
    asm("{ .reg .u64 t; cvta.to.shared.u64 t, %1; cvt.u32.u64 %0, t; }"
        : "=r"(a) : "l"(p));
    return a;
}
__device__ __forceinline__ void ldsm_x4(uint32_t (&r)[4], uint32_t addr) {
    asm volatile("ldmatrix.sync.aligned.m8n8.x4.shared.b16 {%0,%1,%2,%3}, [%4];"
        : "=r"(r[0]), "=r"(r[1]), "=r"(r[2]), "=r"(r[3]) : "r"(addr));
}
__device__ __forceinline__ void mma_f16(float (&d)[4], const uint32_t (&a)[4],
                                        uint32_t b0, uint32_t b1) {
    asm volatile(
        "mma.sync.aligned.m16n8k16.row.col.f32.f16.f16.f32 "
        "{%0,%1,%2,%3}, {%4,%5,%6,%7}, {%8,%9}, {%0,%1,%2,%3};"
        : "+f"(d[0]), "+f"(d[1]), "+f"(d[2]), "+f"(d[3])
        : "r"(a[0]), "r"(a[1]), "r"(a[2]), "r"(a[3]), "r"(b0), "r"(b1));
}
// fp16x2 of relu(u+v) for a float2 (x in low half)
__device__ __forceinline__ uint32_t cvt2h(float2 u, float2 v) {
    float x0 = fmaxf(u.x + v.x, 0.f);
    float x1 = fmaxf(u.y + v.y, 0.f);
    __half2 h = __floats2half2_rn(x0, x1);
    return *reinterpret_cast<uint32_t*>(&h);
}

// ============================================================================
// Kernel 0: aw1^T -> fp16 + zero the output buffer
// ============================================================================
__global__ void k_prep(const float* __restrict__ aw1, float* __restrict__ out) {
    int idx = blockIdx.x * 256 + threadIdx.x;
    if (idx < 1024) out[idx] = 0.f;
    if (idx >= 4096) return;
    int kk = idx & 63, k = idx >> 6;
    float w = aw1[k * 64 + kk];
    g_wh[kk * 64 + k] = __half_as_ushort(__float2half_rn(w));
}

// ============================================================================
// Kernel 1: per-node feature MLP + ui/uj precompute
// ============================================================================
__global__ void k_feat(const float* __restrict__ coords,
                       const float* __restrict__ fw0, const float* __restrict__ fb0,
                       const float* __restrict__ fw1, const float* __restrict__ fb1,
                       const float* __restrict__ aw0, const float* __restrict__ ab0)
{
    int row = blockIdx.x * blockDim.x + threadIdx.x;
    if (row >= NROWS) return;
    float c0 = coords[row * 3 + 0];
    float c1 = coords[row * 3 + 1];
    float c2 = coords[row * 3 + 2];

    float h0[64];
#pragma unroll
    for (int k = 0; k < 64; k++) {
        float v = fb0[k] + c0 * fw0[k] + c1 * fw0[64 + k] + c2 * fw0[128 + k];
        h0[k] = fmaxf(v, 0.f);
        float u = ab0[k] + c0 * aw0[k] + c1 * aw0[64 + k] + c2 * aw0[128 + k];
        g_ui[row * 64 + k] = u;
        float w = c0 * aw0[192 + k] + c1 * aw0[256 + k] + c2 * aw0[320 + k];
        g_uj[row * 64 + k] = w;
    }

    for (int cb = 0; cb < 128; cb += 4) {
        float ax = fb1[cb + 0], ay = fb1[cb + 1], az = fb1[cb + 2], aw = fb1[cb + 3];
#pragma unroll
        for (int k = 0; k < 64; k++) {
            float4 w = *(const float4*)&fw1[k * 128 + cb];
            ax += h0[k] * w.x; ay += h0[k] * w.y;
            az += h0[k] * w.z; aw += h0[k] * w.w;
        }
        ax = fmaxf(ax, 0.f); ay = fmaxf(ay, 0.f);
        az = fmaxf(az, 0.f); aw = fmaxf(aw, 0.f);
        *(float4*)&g_h[row * 128 + cb] = make_float4(ax, ay, az, aw);
        g_upd[row * 259 + cb + 0] = ax;
        g_upd[row * 259 + cb + 1] = ay;
        g_upd[row * 259 + cb + 2] = az;
        g_upd[row * 259 + cb + 3] = aw;
    }
    g_upd[row * 259 + 128] = c0;
    g_upd[row * 259 + 129] = c1;
    g_upd[row * 259 + 130] = c2;
}

// ============================================================================
// Kernel 2: HMMA fused adjacency + aggregation — pure fp16 single pass,
// register-built A fragments, occupancy 3 (latency-bound kernel; R13 showed
// halving MMAs was neutral, so add warps to cover the per-i serial chain).
// ============================================================================
#define TSTR 144                 // W tile row stride, bytes
#define UJS  72                  // uj smem row stride, floats (bank shift 8)
#define OFF_WH   0               // 64*144 = 9216
#define OFF_UJ   9216            // 128*72*4 = 36864
#define OFF_UI   46080           // 8*64*4 = 2048
#define OFF_A    48128           // 8*128*4 = 4096
#define OFF_AB1  52224           // 256
#define OFF_AW2  52480           // 256
#define SMEM_ADJ 52736

__global__ void __launch_bounds__(256, 3) k_adj(
    const float* __restrict__ ab1, const float* __restrict__ aw2,
    const float* __restrict__ ab2)
{
    extern __shared__ char smem[];
    const uint32_t smb = smem_u32(smem);
    float* s_uj  = (float*)(smem + OFF_UJ);
    float* s_ui  = (float*)(smem + OFF_UI);
    float* s_A   = (float*)(smem + OFF_A);
    float* s_ab1 = (float*)(smem + OFF_AB1);
    float* s_aw2 = (float*)(smem + OFF_AW2);

    const int tid  = threadIdx.x;
    const int lane = tid & 31;
    const int wid  = tid >> 5;
    const int b    = blockIdx.x >> 6;
    const int i0   = (blockIdx.x & 63) << 3;

    // stage fp16 W tile ([kk][k], 144B row stride)
    {
        const uint32_t* wh32 = (const uint32_t*)g_wh;
        for (int idx = tid; idx < 2048; idx += 256) {
            int kk = idx >> 5, kp = idx & 31;
            uint32_t off = (uint32_t)(kk * TSTR + kp * 4);
            *(uint32_t*)(smem + OFF_WH + off) = wh32[idx];
        }
    }
    for (int idx = tid; idx < 512; idx += 256)
        s_ui[idx] = g_ui[(size_t)(b * NN + i0 + (idx >> 6)) * 64 + (idx & 63)];
    if (tid < 64) { s_ab1[tid] = ab1[tid]; s_aw2[tid] = aw2[tid]; }
    const float ab2v = ab2[0];

    // fragment addressing
    const int m0 = wid * 16;        // warp's j-row base
    const int g  = lane >> 2;       // mma row group
    const int t  = lane & 3;        // mma k group
    const uint32_t w_row  = (uint32_t)(((lane >> 4) & 1) * 8 + (lane & 7));
    const uint32_t w_koff = (uint32_t)(((lane >> 3) & 1) * 8);
    const uint32_t addrW  = smb + OFF_WH + w_row * TSTR + w_koff * 2;

    // V-phase addressing
    const int c    = tid & 127;
    const int half = tid >> 7;

    float Vacc[4] = {0.f, 0.f, 0.f, 0.f};

    __syncthreads();

    for (int jt = 0; jt < 4; jt++) {
        // stage uj tile (128 x 64 floats, padded stride 72)
        {
            const float2* src = (const float2*)(g_uj + (size_t)(b * NN + jt * 128) * 64);
            for (int idx = tid; idx < 4096; idx += 256) {
                int r = idx >> 5, c2 = idx & 31;
                *(float2*)&s_uj[r * UJS + c2 * 2] = src[idx];
            }
        }
        __syncthreads();

        const float* ujr0 = s_uj + (m0 + g) * UJS;
        const float* ujr1 = s_uj + (m0 + g + 8) * UJS;

        for (int i = 0; i < 8; i++) {
            float acc[8][4];
#pragma unroll
            for (int n = 0; n < 8; n++)
#pragma unroll
                for (int x = 0; x < 4; x++) acc[n][x] = 0.f;

            const float* uib = s_ui + i * 64;

#pragma unroll
            for (int k0 = 0; k0 < 4; k0++) {
                const int col = k0 * 16 + t * 2;
                // ---- A fragments in registers: fp16(relu(ui+uj)) ----
                float2 v0  = *(const float2*)(uib + col);
                float2 v1  = *(const float2*)(uib + col + 8);
                uint32_t Ah[4];
                Ah[0] = cvt2h(*(const float2*)(ujr0 + col),     v0);
                Ah[1] = cvt2h(*(const float2*)(ujr1 + col),     v0);
                Ah[2] = cvt2h(*(const float2*)(ujr0 + col + 8), v1);
                Ah[3] = cvt2h(*(const float2*)(ujr1 + col + 8), v1);

#pragma unroll
                for (int np = 0; np < 4; np++) {
                    uint32_t Bq[4];
                    ldsm_x4(Bq, addrW + (uint32_t)(np * 16 * TSTR) + k0 * 32);
                    mma_f16(acc[2 * np],     Ah, Bq[0], Bq[1]);
                    mma_f16(acc[2 * np + 1], Ah, Bq[2], Bq[3]);
                }
            }

            // ---- epilogue: p[j] = sum_kk relu(a2+ab1)*aw2 ----
            {
                float p0 = 0.f, p1 = 0.f;
#pragma unroll
                for (int n = 0; n < 8; n++) {
                    int kk = n * 8 + t * 2;
                    float b0 = s_ab1[kk], b1 = s_ab1[kk + 1];
                    float w0 = s_aw2[kk], w1 = s_aw2[kk + 1];
                    p0 += fmaxf(acc[n][0] + b0, 0.f) * w0
                        + fmaxf(acc[n][1] + b1, 0.f) * w1;
                    p1 += fmaxf(acc[n][2] + b0, 0.f) * w0
                        + fmaxf(acc[n][3] + b1, 0.f) * w1;
                }
                p0 += __shfl_xor_sync(0xffffffffu, p0, 1);
                p0 += __shfl_xor_sync(0xffffffffu, p0, 2);
                p1 += __shfl_xor_sync(0xffffffffu, p1, 1);
                p1 += __shfl_xor_sync(0xffffffffu, p1, 2);
                if (t == 0) {
                    int j0 = m0 + g;
                    s_A[i * 128 + j0]     = fmaxf(p0 + ab2v, 0.f);
                    s_A[i * 128 + j0 + 8] = fmaxf(p1 + ab2v, 0.f);
                }
            }
        }
        __syncthreads();   // s_A complete before V reads

        // ---- V accumulation: 8 i-rows vs h tile (L2-resident) ----
        {
            const float* hp = g_h + (size_t)(b * NN + jt * 128) * 128 + c;
            const float* sA = s_A + half * 4 * 128;
#pragma unroll 4
            for (int j = 0; j < 128; j++) {
                float hv = __ldg(hp + (size_t)j * 128);
                Vacc[0] += sA[0 * 128 + j] * hv;
                Vacc[1] += sA[1 * 128 + j] * hv;
                Vacc[2] += sA[2 * 128 + j] * hv;
                Vacc[3] += sA[3 * 128 + j] * hv;
            }
        }
        __syncthreads();   // V reads done before next jt's staging
    }

#pragma unroll
    for (int x = 0; x < 4; x++)
        g_upd[(size_t)(b * NN + i0 + half * 4 + x) * 259 + 131 + c] = Vacc[x];
}

// ============================================================================
// Kernel 3: update MLP (259 -> 256 -> 128) with smem-staged weights +
// fused maxpool via atomicMax. 16 rows/CTA, 256 CTAs. (Validated 61us — R10.)
// ============================================================================
#define SMEM_UPD ((16 * 260 + 16 * 260 + 8192) * 4)   // 66048 B

__global__ void __launch_bounds__(256) k_upd(
    const float* __restrict__ uw0, const float* __restrict__ ub0,
    const float* __restrict__ uw1, const float* __restrict__ ub1,
    float* __restrict__ out)
{
    extern __shared__ float smf[];
    float* s_act = smf;                  // 16*260
    float* s_mid = smf + 16 * 260;       // 16*260
    float* s_w   = smf + 2 * 16 * 260;   // 8192

    const int tid = threadIdx.x;
    const int r0 = blockIdx.x * 16;
    const int bb = r0 >> 9;              // batch index

    for (int idx = tid; idx < 16 * 259; idx += 256) {
        int r = idx / 259, cc = idx - r * 259;
        s_act[r * 260 + cc] = g_upd[(size_t)(r0 + r) * 259 + cc];
    }

    const int cg = tid & 31;
    const int rg = tid >> 5;

    // ---- GEMM1: (16x259) @ (259x256), W chunked through smem ----
    float acc[2][8];
#pragma unroll
    for (int x = 0; x < 2; x++)
#pragma unroll
        for (int q = 0; q < 8; q++) acc[x][q] = 0.f;

    for (int kb = 0; kb < 259; kb += 32) {
        int cs = (259 - kb < 32) ? (259 - kb) : 32;
        __syncthreads();
        for (int idx = tid; idx < cs * 64; idx += 256) {
            int kk = idx >> 6, cc = idx & 63;
            ((float4*)(s_w + kk * 256))[cc] =
                ((const float4*)(uw0 + (size_t)(kb + kk) * 256))[cc];
        }
        __syncthreads();
        for (int k = 0; k < cs; k++) {
            float a0 = s_act[(rg * 2 + 0) * 260 + kb + k];
            float a1 = s_act[(rg * 2 + 1) * 260 + kb + k];
            float4 w0 = *(const float4*)&s_w[k * 256 + cg * 4];
            float4 w1 = *(const float4*)&s_w[k * 256 + 128 + cg * 4];
            acc[0][0] += a0 * w0.x; acc[0][1] += a0 * w0.y;
            acc[0][2] += a0 * w0.z; acc[0][3] += a0 * w0.w;
            acc[0][4] += a0 * w1.x; acc[0][5] += a0 * w1.y;
            acc[0][6] += a0 * w1.z; acc[0][7] += a0 * w1.w;
            acc[1][0] += a1 * w0.x; acc[1][1] += a1 * w0.y;
            acc[1][2] += a1 * w0.z; acc[1][3] += a1 * w0.w;
            acc[1][4] += a1 * w1.x; acc[1][5] += a1 * w1.y;
            acc[1][6] += a1 * w1.z; acc[1][7] += a1 * w1.w;
        }
    }
    {
        float b0 = __ldg(&ub0[cg * 4 + 0]), b1 = __ldg(&ub0[cg * 4 + 1]);
        float b2 = __ldg(&ub0[cg * 4 + 2]), b3 = __ldg(&ub0[cg * 4 + 3]);
        float b4 = __ldg(&ub0[128 + cg * 4 + 0]), b5 = __ldg(&ub0[128 + cg * 4 + 1]);
        float b6 = __ldg(&ub0[128 + cg * 4 + 2]), b7 = __ldg(&ub0[128 + cg * 4 + 3]);
#pragma unroll
        for (int x = 0; x < 2; x++) {
            int row = rg * 2 + x;
            float4 lo = make_float4(fmaxf(acc[x][0] + b0, 0.f), fmaxf(acc[x][1] + b1, 0.f),
                                    fmaxf(acc[x][2] + b2, 0.f), fmaxf(acc[x][3] + b3, 0.f));
            float4 hi = make_float4(fmaxf(acc[x][4] + b4, 0.f), fmaxf(acc[x][5] + b5, 0.f),
                                    fmaxf(acc[x][6] + b6, 0.f), fmaxf(acc[x][7] + b7, 0.f));
            *(float4*)&s_mid[row * 260 + cg * 4] = lo;
            *(float4*)&s_mid[row * 260 + 128 + cg * 4] = hi;
        }
    }

    // ---- GEMM2: (16x256) @ (256x128), W chunked ----
    float acc2[2][4];
#pragma unroll
    for (int x = 0; x < 2; x++)
#pragma unroll
        for (int q = 0; q < 4; q++) acc2[x][q] = 0.f;

    for (int kb = 0; kb < 256; kb += 32) {
        __syncthreads();
        for (int idx = tid; idx < 32 * 32; idx += 256) {
            int kk = idx >> 5, cc = idx & 31;
            ((float4*)(s_w + kk * 128))[cc] =
                ((const float4*)(uw1 + (size_t)(kb + kk) * 128))[cc];
        }
        __syncthreads();
        for (int k = 0; k < 32; k++) {
            float a0 = s_mid[(rg * 2 + 0) * 260 + kb + k];
            float a1 = s_mid[(rg * 2 + 1) * 260 + kb + k];
            float4 w = *(const float4*)&s_w[k * 128 + cg * 4];
            acc2[0][0] += a0 * w.x; acc2[0][1] += a0 * w.y;
            acc2[0][2] += a0 * w.z; acc2[0][3] += a0 * w.w;
            acc2[1][0] += a1 * w.x; acc2[1][1] += a1 * w.y;
            acc2[1][2] += a1 * w.z; acc2[1][3] += a1 * w.w;
        }
    }

    // ---- epilogue + fused maxpool (local reduce then atomicMax) ----
    {
        float b0 = __ldg(&ub1[cg * 4 + 0]), b1 = __ldg(&ub1[cg * 4 + 1]);
        float b2 = __ldg(&ub1[cg * 4 + 2]), b3 = __ldg(&ub1[cg * 4 + 3]);
        float m0 = 0.f, m1 = 0.f, m2 = 0.f, m3 = 0.f;
#pragma unroll
        for (int x = 0; x < 2; x++) {
            m0 = fmaxf(m0, fmaxf(acc2[x][0] + b0, 0.f));
            m1 = fmaxf(m1, fmaxf(acc2[x][1] + b1, 0.f));
            m2 = fmaxf(m2, fmaxf(acc2[x][2] + b2, 0.f));
            m3 = fmaxf(m3, fmaxf(acc2[x][3] + b3, 0.f));
        }
        __syncthreads();   // s_act no longer needed; reuse as reduction pad
        *(float4*)&s_act[rg * 128 + cg * 4] = make_float4(m0, m1, m2, m3);
    }
    __syncthreads();
    if (tid < 128) {
        float m = s_act[tid];
#pragma unroll
        for (int g2 = 1; g2 < 8; g2++) m = fmaxf(m, s_act[g2 * 128 + tid]);
        atomicMax((int*)&out[bb * 128 + tid], __float_as_int(m));
    }
}

// ============================================================================
extern "C" void kernel_launch(void* const* d_in, const int* in_sizes, int n_in,
                              void* d_out, int out_size)
{
    const float* coords = (const float*)d_in[0];
    const float* fw0 = (const float*)d_in[1];
    const float* fb0 = (const float*)d_in[2];
    const float* fw1 = (const float*)d_in[3];
    const float* fb1 = (const float*)d_in[4];
    const float* aw0 = (const float*)d_in[5];
    const float* ab0 = (const float*)d_in[6];
    const float* aw1 = (const float*)d_in[7];
    const float* ab1 = (const float*)d_in[8];
    const float* aw2 = (const float*)d_in[9];
    const float* ab2 = (const float*)d_in[10];
    const float* uw0 = (const float*)d_in[11];
    const float* ub0 = (const float*)d_in[12];
    const float* uw1 = (const float*)d_in[13];
    const float* ub1 = (const float*)d_in[14];
    float* out = (float*)d_out;

    static int attr_set = 0;
    if (!attr_set) {
        cudaFuncSetAttribute(k_adj, cudaFuncAttributeMaxDynamicSharedMemorySize, SMEM_ADJ);
        cudaFuncSetAttribute(k_upd, cudaFuncAttributeMaxDynamicSharedMemorySize, SMEM_UPD);
        attr_set = 1;
    }

    k_prep<<<16, 256>>>(aw1, out);
    k_feat<<<32, 128>>>(coords, fw0, fb0, fw1, fb1, aw0, ab0);
    k_adj<<<512, 256, SMEM_ADJ>>>(ab1, aw2, ab2);
    k_upd<<<256, 256, SMEM_UPD>>>(uw0, ub0, uw1, ub1, out);
}

// round 17
// speedup vs baseline: 1.4790x; 1.4790x over previous
#include <cuda_runtime.h>
#include <cuda_fp16.h>
#include <cstdint>

#define BB 8
#define NN 512
#define NROWS (BB * NN)   // 4096

// ---------------- scratch (device globals; no allocation allowed) ----------
__device__ float g_h[NROWS * 128];
__device__ float g_ui[NROWS * 64];
__device__ float g_uj[NROWS * 64];
__device__ float g_upd[NROWS * 259];
__device__ unsigned short g_wh[64 * 64];   // aw1^T fp16, [kk][k]

// ---------------- helpers ---------------------------------------------------
__device__ __forceinline__ uint32_t smem_u32(const void* p) {
    uint32_t a;
    asm("{ .reg .u64 t; cvta.to.shared.u64 t, %1; cvt.u32.u64 %0, t; }"
        : "=r"(a) : "l"(p));
    return a;
}
__device__ __forceinline__ void ldsm_x4(uint32_t (&r)[4], uint32_t addr) {
    asm volatile("ldmatrix.sync.aligned.m8n8.x4.shared.b16 {%0,%1,%2,%3}, [%4];"
        : "=r"(r[0]), "=r"(r[1]), "=r"(r[2]), "=r"(r[3]) : "r"(addr));
}
__device__ __forceinline__ void mma_f16(float (&d)[4], const uint32_t (&a)[4],
                                        uint32_t b0, uint32_t b1) {
    asm volatile(
        "mma.sync.aligned.m16n8k16.row.col.f32.f16.f16.f32 "
        "{%0,%1,%2,%3}, {%4,%5,%6,%7}, {%8,%9}, {%0,%1,%2,%3};"
        : "+f"(d[0]), "+f"(d[1]), "+f"(d[2]), "+f"(d[3])
        : "r"(a[0]), "r"(a[1]), "r"(a[2]), "r"(a[3]), "r"(b0), "r"(b1));
}
// fp16x2 of relu(u+v) for a float2 (x in low half)
__device__ __forceinline__ uint32_t cvt2h(float2 u, float2 v) {
    float x0 = fmaxf(u.x + v.x, 0.f);
    float x1 = fmaxf(u.y + v.y, 0.f);
    __half2 h = __floats2half2_rn(x0, x1);
    return *reinterpret_cast<uint32_t*>(&h);
}

// ============================================================================
// Kernel 0: aw1^T -> fp16 + zero the output buffer
// ============================================================================
__global__ void k_prep(const float* __restrict__ aw1, float* __restrict__ out) {
    int idx = blockIdx.x * 256 + threadIdx.x;
    if (idx < 1024) out[idx] = 0.f;
    if (idx >= 4096) return;
    int kk = idx & 63, k = idx >> 6;
    float w = aw1[k * 64 + kk];
    g_wh[kk * 64 + k] = __half_as_ushort(__float2half_rn(w));
}

// ============================================================================
// Kernel 1: per-node feature MLP + ui/uj precompute
// ============================================================================
__global__ void k_feat(const float* __restrict__ coords,
                       const float* __restrict__ fw0, const float* __restrict__ fb0,
                       const float* __restrict__ fw1, const float* __restrict__ fb1,
                       const float* __restrict__ aw0, const float* __restrict__ ab0)
{
    int row = blockIdx.x * blockDim.x + threadIdx.x;
    if (row >= NROWS) return;
    float c0 = coords[row * 3 + 0];
    float c1 = coords[row * 3 + 1];
    float c2 = coords[row * 3 + 2];

    float h0[64];
#pragma unroll
    for (int k = 0; k < 64; k++) {
        float v = fb0[k] + c0 * fw0[k] + c1 * fw0[64 + k] + c2 * fw0[128 + k];
        h0[k] = fmaxf(v, 0.f);
        float u = ab0[k] + c0 * aw0[k] + c1 * aw0[64 + k] + c2 * aw0[128 + k];
        g_ui[row * 64 + k] = u;
        float w = c0 * aw0[192 + k] + c1 * aw0[256 + k] + c2 * aw0[320 + k];
        g_uj[row * 64 + k] = w;
    }

    for (int cb = 0; cb < 128; cb += 4) {
        float ax = fb1[cb + 0], ay = fb1[cb + 1], az = fb1[cb + 2], aw = fb1[cb + 3];
#pragma unroll
        for (int k = 0; k < 64; k++) {
            float4 w = *(const float4*)&fw1[k * 128 + cb];
            ax += h0[k] * w.x; ay += h0[k] * w.y;
            az += h0[k] * w.z; aw += h0[k] * w.w;
        }
        ax = fmaxf(ax, 0.f); ay = fmaxf(ay, 0.f);
        az = fmaxf(az, 0.f); aw = fmaxf(aw, 0.f);
        *(float4*)&g_h[row * 128 + cb] = make_float4(ax, ay, az, aw);
        g_upd[row * 259 + cb + 0] = ax;
        g_upd[row * 259 + cb + 1] = ay;
        g_upd[row * 259 + cb + 2] = az;
        g_upd[row * 259 + cb + 3] = aw;
    }
    g_upd[row * 259 + 128] = c0;
    g_upd[row * 259 + 129] = c1;
    g_upd[row * 259 + 130] = c2;
}

// ============================================================================
// Kernel 2: HMMA fused adjacency + aggregation — pure fp16 single pass,
// register-built A fragments, occupancy 2 (occ-3 spilled; occ-2 validated).
// ============================================================================
#define TSTR 144                 // W tile row stride, bytes
#define UJS  72                  // uj smem row stride, floats (bank shift 8)
#define OFF_WH   0               // 64*144 = 9216
#define OFF_UJ   9216            // 128*72*4 = 36864
#define OFF_UI   46080           // 8*64*4 = 2048
#define OFF_A    48128           // 8*128*4 = 4096
#define OFF_AB1  52224           // 256
#define OFF_AW2  52480           // 256
#define SMEM_ADJ 52736

__global__ void __launch_bounds__(256, 2) k_adj(
    const float* __restrict__ ab1, const float* __restrict__ aw2,
    const float* __restrict__ ab2)
{
    extern __shared__ char smem[];
    const uint32_t smb = smem_u32(smem);
    float* s_uj  = (float*)(smem + OFF_UJ);
    float* s_ui  = (float*)(smem + OFF_UI);
    float* s_A   = (float*)(smem + OFF_A);
    float* s_ab1 = (float*)(smem + OFF_AB1);
    float* s_aw2 = (float*)(smem + OFF_AW2);

    const int tid  = threadIdx.x;
    const int lane = tid & 31;
    const int wid  = tid >> 5;
    const int b    = blockIdx.x >> 6;
    const int i0   = (blockIdx.x & 63) << 3;

    // stage fp16 W tile ([kk][k], 144B row stride)
    {
        const uint32_t* wh32 = (const uint32_t*)g_wh;
        for (int idx = tid; idx < 2048; idx += 256) {
            int kk = idx >> 5, kp = idx & 31;
            uint32_t off = (uint32_t)(kk * TSTR + kp * 4);
            *(uint32_t*)(smem + OFF_WH + off) = wh32[idx];
        }
    }
    for (int idx = tid; idx < 512; idx += 256)
        s_ui[idx] = g_ui[(size_t)(b * NN + i0 + (idx >> 6)) * 64 + (idx & 63)];
    if (tid < 64) { s_ab1[tid] = ab1[tid]; s_aw2[tid] = aw2[tid]; }
    const float ab2v = ab2[0];

    // fragment addressing
    const int m0 = wid * 16;        // warp's j-row base
    const int g  = lane >> 2;       // mma row group
    const int t  = lane & 3;        // mma k group
    const uint32_t w_row  = (uint32_t)(((lane >> 4) & 1) * 8 + (lane & 7));
    const uint32_t w_koff = (uint32_t)(((lane >> 3) & 1) * 8);
    const uint32_t addrW  = smb + OFF_WH + w_row * TSTR + w_koff * 2;

    // V-phase addressing
    const int c    = tid & 127;
    const int half = tid >> 7;

    float Vacc[4] = {0.f, 0.f, 0.f, 0.f};

    __syncthreads();

    for (int jt = 0; jt < 4; jt++) {
        // stage uj tile (128 x 64 floats, padded stride 72)
        {
            const float2* src = (const float2*)(g_uj + (size_t)(b * NN + jt * 128) * 64);
            for (int idx = tid; idx < 4096; idx += 256) {
                int r = idx >> 5, c2 = idx & 31;
                *(float2*)&s_uj[r * UJS + c2 * 2] = src[idx];
            }
        }
        __syncthreads();

        const float* ujr0 = s_uj + (m0 + g) * UJS;
        const float* ujr1 = s_uj + (m0 + g + 8) * UJS;

        for (int i = 0; i < 8; i++) {
            float acc[8][4];
#pragma unroll
            for (int n = 0; n < 8; n++)
#pragma unroll
                for (int x = 0; x < 4; x++) acc[n][x] = 0.f;

            const float* uib = s_ui + i * 64;

#pragma unroll
            for (int k0 = 0; k0 < 4; k0++) {
                const int col = k0 * 16 + t * 2;
                // ---- A fragments in registers: fp16(relu(ui+uj)) ----
                float2 v0  = *(const float2*)(uib + col);
                float2 v1  = *(const float2*)(uib + col + 8);
                uint32_t Ah[4];
                Ah[0] = cvt2h(*(const float2*)(ujr0 + col),     v0);
                Ah[1] = cvt2h(*(const float2*)(ujr1 + col),     v0);
                Ah[2] = cvt2h(*(const float2*)(ujr0 + col + 8), v1);
                Ah[3] = cvt2h(*(const float2*)(ujr1 + col + 8), v1);

#pragma unroll
                for (int np = 0; np < 4; np++) {
                    uint32_t Bq[4];
                    ldsm_x4(Bq, addrW + (uint32_t)(np * 16 * TSTR) + k0 * 32);
                    mma_f16(acc[2 * np],     Ah, Bq[0], Bq[1]);
                    mma_f16(acc[2 * np + 1], Ah, Bq[2], Bq[3]);
                }
            }

            // ---- epilogue: p[j] = sum_kk relu(a2+ab1)*aw2 ----
            {
                float p0 = 0.f, p1 = 0.f;
#pragma unroll
                for (int n = 0; n < 8; n++) {
                    int kk = n * 8 + t * 2;
                    float b0 = s_ab1[kk], b1 = s_ab1[kk + 1];
                    float w0 = s_aw2[kk], w1 = s_aw2[kk + 1];
                    p0 += fmaxf(acc[n][0] + b0, 0.f) * w0
                        + fmaxf(acc[n][1] + b1, 0.f) * w1;
                    p1 += fmaxf(acc[n][2] + b0, 0.f) * w0
                        + fmaxf(acc[n][3] + b1, 0.f) * w1;
                }
                p0 += __shfl_xor_sync(0xffffffffu, p0, 1);
                p0 += __shfl_xor_sync(0xffffffffu, p0, 2);
                p1 += __shfl_xor_sync(0xffffffffu, p1, 1);
                p1 += __shfl_xor_sync(0xffffffffu, p1, 2);
                if (t == 0) {
                    int j0 = m0 + g;
                    s_A[i * 128 + j0]     = fmaxf(p0 + ab2v, 0.f);
                    s_A[i * 128 + j0 + 8] = fmaxf(p1 + ab2v, 0.f);
                }
            }
        }
        __syncthreads();   // s_A complete before V reads

        // ---- V accumulation: 8 i-rows vs h tile (L2-resident) ----
        {
            const float* hp = g_h + (size_t)(b * NN + jt * 128) * 128 + c;
            const float* sA = s_A + half * 4 * 128;
#pragma unroll 4
            for (int j = 0; j < 128; j++) {
                float hv = __ldg(hp + (size_t)j * 128);
                Vacc[0] += sA[0 * 128 + j] * hv;
                Vacc[1] += sA[1 * 128 + j] * hv;
                Vacc[2] += sA[2 * 128 + j] * hv;
                Vacc[3] += sA[3 * 128 + j] * hv;
            }
        }
        __syncthreads();   // V reads done before next jt's staging
    }

#pragma unroll
    for (int x = 0; x < 4; x++)
        g_upd[(size_t)(b * NN + i0 + half * 4 + x) * 259 + 131 + c] = Vacc[x];
}

// ============================================================================
// Kernel 3: update MLP (259 -> 256 -> 128) with smem-staged weights +
// fused maxpool via atomicMax. 16 rows/CTA, 256 CTAs. (Best measured: 61us.)
// ============================================================================
#define SMEM_UPD ((16 * 260 + 16 * 260 + 8192) * 4)   // 66048 B

__global__ void __launch_bounds__(256) k_upd(
    const float* __restrict__ uw0, const float* __restrict__ ub0,
    const float* __restrict__ uw1, const float* __restrict__ ub1,
    float* __restrict__ out)
{
    extern __shared__ float smf[];
    float* s_act = smf;                  // 16*260
    float* s_mid = smf + 16 * 260;       // 16*260
    float* s_w   = smf + 2 * 16 * 260;   // 8192

    const int tid = threadIdx.x;
    const int r0 = blockIdx.x * 16;
    const int bb = r0 >> 9;              // batch index

    for (int idx = tid; idx < 16 * 259; idx += 256) {
        int r = idx / 259, cc = idx - r * 259;
        s_act[r * 260 + cc] = g_upd[(size_t)(r0 + r) * 259 + cc];
    }

    const int cg = tid & 31;
    const int rg = tid >> 5;

    // ---- GEMM1: (16x259) @ (259x256), W chunked through smem ----
    float acc[2][8];
#pragma unroll
    for (int x = 0; x < 2; x++)
#pragma unroll
        for (int q = 0; q < 8; q++) acc[x][q] = 0.f;

    for (int kb = 0; kb < 259; kb += 32) {
        int cs = (259 - kb < 32) ? (259 - kb) : 32;
        __syncthreads();
        for (int idx = tid; idx < cs * 64; idx += 256) {
            int kk = idx >> 6, cc = idx & 63;
            ((float4*)(s_w + kk * 256))[cc] =
                ((const float4*)(uw0 + (size_t)(kb + kk) * 256))[cc];
        }
        __syncthreads();
        for (int k = 0; k < cs; k++) {
            float a0 = s_act[(rg * 2 + 0) * 260 + kb + k];
            float a1 = s_act[(rg * 2 + 1) * 260 + kb + k];
            float4 w0 = *(const float4*)&s_w[k * 256 + cg * 4];
            float4 w1 = *(const float4*)&s_w[k * 256 + 128 + cg * 4];
            acc[0][0] += a0 * w0.x; acc[0][1] += a0 * w0.y;
            acc[0][2] += a0 * w0.z; acc[0][3] += a0 * w0.w;
            acc[0][4] += a0 * w1.x; acc[0][5] += a0 * w1.y;
            acc[0][6] += a0 * w1.z; acc[0][7] += a0 * w1.w;
            acc[1][0] += a1 * w0.x; acc[1][1] += a1 * w0.y;
            acc[1][2] += a1 * w0.z; acc[1][3] += a1 * w0.w;
            acc[1][4] += a1 * w1.x; acc[1][5] += a1 * w1.y;
            acc[1][6] += a1 * w1.z; acc[1][7] += a1 * w1.w;
        }
    }
    {
        float b0 = __ldg(&ub0[cg * 4 + 0]), b1 = __ldg(&ub0[cg * 4 + 1]);
        float b2 = __ldg(&ub0[cg * 4 + 2]), b3 = __ldg(&ub0[cg * 4 + 3]);
        float b4 = __ldg(&ub0[128 + cg * 4 + 0]), b5 = __ldg(&ub0[128 + cg * 4 + 1]);
        float b6 = __ldg(&ub0[128 + cg * 4 + 2]), b7 = __ldg(&ub0[128 + cg * 4 + 3]);
#pragma unroll
        for (int x = 0; x < 2; x++) {
            int row = rg * 2 + x;
            float4 lo = make_float4(fmaxf(acc[x][0] + b0, 0.f), fmaxf(acc[x][1] + b1, 0.f),
                                    fmaxf(acc[x][2] + b2, 0.f), fmaxf(acc[x][3] + b3, 0.f));
            float4 hi = make_float4(fmaxf(acc[x][4] + b4, 0.f), fmaxf(acc[x][5] + b5, 0.f),
                                    fmaxf(acc[x][6] + b6, 0.f), fmaxf(acc[x][7] + b7, 0.f));
            *(float4*)&s_mid[row * 260 + cg * 4] = lo;
            *(float4*)&s_mid[row * 260 + 128 + cg * 4] = hi;
        }
    }

    // ---- GEMM2: (16x256) @ (256x128), W chunked ----
    float acc2[2][4];
#pragma unroll
    for (int x = 0; x < 2; x++)
#pragma unroll
        for (int q = 0; q < 4; q++) acc2[x][q] = 0.f;

    for (int kb = 0; kb < 256; kb += 32) {
        __syncthreads();
        for (int idx = tid; idx < 32 * 32; idx += 256) {
            int kk = idx >> 5, cc = idx & 31;
            ((float4*)(s_w + kk * 128))[cc] =
                ((const float4*)(uw1 + (size_t)(kb + kk) * 128))[cc];
        }
        __syncthreads();
        for (int k = 0; k < 32; k++) {
            float a0 = s_mid[(rg * 2 + 0) * 260 + kb + k];
            float a1 = s_mid[(rg * 2 + 1) * 260 + kb + k];
            float4 w = *(const float4*)&s_w[k * 128 + cg * 4];
            acc2[0][0] += a0 * w.x; acc2[0][1] += a0 * w.y;
            acc2[0][2] += a0 * w.z; acc2[0][3] += a0 * w.w;
            acc2[1][0] += a1 * w.x; acc2[1][1] += a1 * w.y;
            acc2[1][2] += a1 * w.z; acc2[1][3] += a1 * w.w;
        }
    }

    // ---- epilogue + fused maxpool (local reduce then atomicMax) ----
    {
        float b0 = __ldg(&ub1[cg * 4 + 0]), b1 = __ldg(&ub1[cg * 4 + 1]);
        float b2 = __ldg(&ub1[cg * 4 + 2]), b3 = __ldg(&ub1[cg * 4 + 3]);
        float m0 = 0.f, m1 = 0.f, m2 = 0.f, m3 = 0.f;
#pragma unroll
        for (int x = 0; x < 2; x++) {
            m0 = fmaxf(m0, fmaxf(acc2[x][0] + b0, 0.f));
            m1 = fmaxf(m1, fmaxf(acc2[x][1] + b1, 0.f));
            m2 = fmaxf(m2, fmaxf(acc2[x][2] + b2, 0.f));
            m3 = fmaxf(m3, fmaxf(acc2[x][3] + b3, 0.f));
        }
        __syncthreads();   // s_act no longer needed; reuse as reduction pad
        *(float4*)&s_act[rg * 128 + cg * 4] = make_float4(m0, m1, m2, m3);
    }
    __syncthreads();
    if (tid < 128) {
        float m = s_act[tid];
#pragma unroll
        for (int g2 = 1; g2 < 8; g2++) m = fmaxf(m, s_act[g2 * 128 + tid]);
        atomicMax((int*)&out[bb * 128 + tid], __float_as_int(m));
    }
}

// ============================================================================
extern "C" void kernel_launch(void* const* d_in, const int* in_sizes, int n_in,
                              void* d_out, int out_size)
{
    const float* coords = (const float*)d_in[0];
    const float* fw0 = (const float*)d_in[1];
    const float* fb0 = (const float*)d_in[2];
    const float* fw1 = (const float*)d_in[3];
    const float* fb1 = (const float*)d_in[4];
    const float* aw0 = (const float*)d_in[5];
    const float* ab0 = (const float*)d_in[6];
    const float* aw1 = (const float*)d_in[7];
    const float* ab1 = (const float*)d_in[8];
    const float* aw2 = (const float*)d_in[9];
    const float* ab2 = (const float*)d_in[10];
    const float* uw0 = (const float*)d_in[11];
    const float* ub0 = (const float*)d_in[12];
    const float* uw1 = (const float*)d_in[13];
    const float* ub1 = (const float*)d_in[14];
    float* out = (float*)d_out;

    static int attr_set = 0;
    if (!attr_set) {
        cudaFuncSetAttribute(k_adj, cudaFuncAttributeMaxDynamicSharedMemorySize, SMEM_ADJ);
        cudaFuncSetAttribute(k_upd, cudaFuncAttributeMaxDynamicSharedMemorySize, SMEM_UPD);
        attr_set = 1;
    }

    k_prep<<<16, 256>>>(aw1, out);
    k_feat<<<32, 128>>>(coords, fw0, fb0, fw1, fb1, aw0, ab0);
    k_adj<<<512, 256, SMEM_ADJ>>>(ab1, aw2, ab2);
    k_upd<<<256, 256, SMEM_UPD>>>(uw0, ub0, uw1, ub1, out);
}